// round 16
// baseline (speedup 1.0000x reference)
#include <cuda_runtime.h>
#include <cuda_fp16.h>
#include <cstdint>

// Problem constants
#define B_   8
#define T_   1024
#define Cc_  1024
#define H_   16
#define D_   64
#define BH_  (B_*H_)     // 128
#define M_   (B_*T_)     // 8192
#define N3_  3072
#define KB_  Cc_         // 1024

// Scratch (static device globals: allocation-free)
__device__ __half g_Qf[(size_t)BH_*T_*D_];
__device__ __half g_Kf[(size_t)BH_*T_*D_];
__device__ __half g_Vf[(size_t)BH_*T_*D_];
__device__ __half g_A[(size_t)M_*Cc_];       // acts fp16: x for QKV, then O for proj
__device__ __half g_Bqkv[(size_t)N3_*KB_];
__device__ __half g_Bout[(size_t)Cc_*KB_];

// ---------------------------------------------------------------------------
__device__ __forceinline__ uint32_t smem_u32(const void* p) {
    uint32_t a;
    asm("{ .reg .u64 t; cvta.to.shared.u64 t, %1; cvt.u32.u64 %0, t; }"
        : "=r"(a) : "l"(p));
    return a;
}
__device__ __forceinline__ void ldsm_x4(uint32_t& r0, uint32_t& r1,
                                        uint32_t& r2, uint32_t& r3, uint32_t addr) {
    asm volatile("ldmatrix.sync.aligned.m8n8.x4.shared.b16 {%0,%1,%2,%3}, [%4];"
                 : "=r"(r0), "=r"(r1), "=r"(r2), "=r"(r3) : "r"(addr));
}
__device__ __forceinline__ void ldsm_x4_t(uint32_t& r0, uint32_t& r1,
                                          uint32_t& r2, uint32_t& r3, uint32_t addr) {
    asm volatile("ldmatrix.sync.aligned.m8n8.x4.trans.shared.b16 {%0,%1,%2,%3}, [%4];"
                 : "=r"(r0), "=r"(r1), "=r"(r2), "=r"(r3) : "r"(addr));
}
__device__ __forceinline__ void mma_f16(float* d, uint32_t a0, uint32_t a1,
                                        uint32_t a2, uint32_t a3,
                                        uint32_t b0, uint32_t b1) {
    asm volatile(
        "mma.sync.aligned.m16n8k16.row.col.f32.f16.f16.f32 "
        "{%0,%1,%2,%3}, {%4,%5,%6,%7}, {%8,%9}, {%0,%1,%2,%3};"
        : "+f"(d[0]), "+f"(d[1]), "+f"(d[2]), "+f"(d[3])
        : "r"(a0), "r"(a1), "r"(a2), "r"(a3), "r"(b0), "r"(b1));
}
__device__ __forceinline__ void cp_async16(uint32_t saddr, const void* gaddr) {
    asm volatile("cp.async.cg.shared.global [%0], [%1], 16;"
                 :: "r"(saddr), "l"(gaddr));
}
#define CP_COMMIT() asm volatile("cp.async.commit_group;" ::: "memory")
#define CP_WAIT(n)  asm volatile("cp.async.wait_group %0;" :: "n"(n) : "memory")

__device__ __forceinline__ uint32_t pack_h2(__half a, __half b) {
    return (uint32_t)__half_as_ushort(a) | ((uint32_t)__half_as_ushort(b) << 16);
}

// ---------------------------------------------------------------------------
// Fused conversion kernel: blocks [0,4096) x->g_A (8 floats/thread);
// [4096,7168) Wqkv->g_Bqkv; [7168,8192) Wout->g_Bout.
// ---------------------------------------------------------------------------
__global__ __launch_bounds__(256)
void conv_all(const float* __restrict__ x,
              const float* __restrict__ Wq,
              const float* __restrict__ Wo)
{
    __shared__ float tile[32][33];
    const int t = threadIdx.x;
    const int b = blockIdx.x;

    if (b < 4096) {            // activations: 8 floats -> 8 halves (16B store)
        int idx = b * 256 + t;            // over M*K/8
        int m  = idx >> 7;                 // K/8 = 128 chunks per row
        int k8 = (idx & 127) << 3;
        const float* src = x + (size_t)m * Cc_ + k8;
        float4 v0 = *(const float4*)(src);
        float4 v1 = *(const float4*)(src + 4);
        uint4 w;
        w.x = pack_h2(__float2half(v0.x), __float2half(v0.y));
        w.y = pack_h2(__float2half(v0.z), __float2half(v0.w));
        w.z = pack_h2(__float2half(v1.x), __float2half(v1.y));
        w.w = pack_h2(__float2half(v1.z), __float2half(v1.w));
        *(uint4*)(g_A + (size_t)m * Cc_ + k8) = w;
        return;
    }

    const float* W;
    __half* Bt;
    int N, bi;
    if (b < 4096 + 3072) { bi = b - 4096;        W = Wq; Bt = g_Bqkv; N = N3_; }
    else                 { bi = b - 4096 - 3072; W = Wo; Bt = g_Bout; N = Cc_; }
    const int k0 = (bi & 31) * 32;
    const int n0 = (bi >> 5) * 32;
#pragma unroll
    for (int i = 0; i < 4; i++) {
        int r = (t >> 5) + i * 8;
        int c = t & 31;
        tile[r][c] = W[(size_t)(k0 + r) * N + n0 + c];
    }
    __syncthreads();
#pragma unroll
    for (int i = 0; i < 4; i++) {
        int nr = (t >> 5) + i * 8;
        int kc = t & 31;
        Bt[(size_t)(n0 + nr) * KB_ + k0 + kc] = __float2half(tile[kc][nr]);
    }
}

// ---------------------------------------------------------------------------
// QKV GEMM: 128x128 CTA tile, BK=64, 8 warps (4M x 2N, warp 32x64), 3-stage
// cp.async, one barrier per chunk. Epilogue -> Q(x0.125*log2e)/K/V fp16.
// ---------------------------------------------------------------------------
#define TSTRIDE 72
#define TILE_B  (128*TSTRIDE*2)          // 18432
#define STAGE_B (2*TILE_B)               // 36864
#define NSTAGE  3
#define GSMEM_TOTAL (NSTAGE*STAGE_B)     // 110592
#define NCHB    (KB_/64)                 // 16
#define QSCALE  (0.125f * 1.4426950408889634f)   // 1/sqrt(D) * log2(e)

__global__ __launch_bounds__(256)
void qkv_kernel(const float* __restrict__ bias)
{
    extern __shared__ char smc[];
    const uint32_t sb = smem_u32(smc);
    const int tid = threadIdx.x;
    const int wid = tid >> 5, lane = tid & 31;
    const int bx = blockIdx.x, by = blockIdx.y;
    const int wm = wid & 3;
    const int wn = wid >> 2;

    const __half* Abf = g_A + (size_t)(by * 128) * KB_;
    const __half* Bbf = g_Bqkv + (size_t)(bx * 128) * KB_;

    const int lrow = tid >> 3;
    const int lch  = tid & 7;
    const uint32_t sOff = (uint32_t)(lrow * TSTRIDE * 2 + lch * 16);

    float acc[2][8][4];
#pragma unroll
    for (int i = 0; i < 2; i++)
#pragma unroll
        for (int j = 0; j < 8; j++)
#pragma unroll
            for (int v = 0; v < 4; v++) acc[i][j][v] = 0.f;

    const int a_row = (lane & 7) + ((lane >> 3) & 1) * 8;
    const int a_col = (lane >> 4) * 8;
    const int b_row = (lane & 7) + (lane >> 4) * 8;
    const int b_col = ((lane >> 3) & 1) * 8;
    const uint32_t aBaseRow = (uint32_t)(wm * 32 + a_row);
    const uint32_t bBaseRow = (uint32_t)(wn * 64 + b_row);

    auto load_stage = [&](int st, int ch) {
        const uint32_t sA = sb + st * STAGE_B + sOff;
        const uint32_t sB = sA + TILE_B;
        const __half* Ag = Abf + (size_t)lrow * KB_ + ch * 64 + lch * 8;
        const __half* Bg = Bbf + (size_t)lrow * KB_ + ch * 64 + lch * 8;
#pragma unroll
        for (int i = 0; i < 4; i++) {
            cp_async16(sA + i * 32 * TSTRIDE * 2, Ag + (size_t)(i * 32) * KB_);
            cp_async16(sB + i * 32 * TSTRIDE * 2, Bg + (size_t)(i * 32) * KB_);
        }
    };

#pragma unroll
    for (int s = 0; s < NSTAGE - 1; ++s) {
        load_stage(s, s);
        CP_COMMIT();
    }

    for (int ch = 0; ch < NCHB; ++ch) {
        CP_WAIT(NSTAGE - 2);
        __syncthreads();

        const int lc = ch + NSTAGE - 1;
        if (lc < NCHB) load_stage(lc % NSTAGE, lc);
        CP_COMMIT();

        const uint32_t sAp = sb + (ch % NSTAGE) * STAGE_B;
        const uint32_t sBp = sAp + TILE_B;
#pragma unroll
        for (int kk = 0; kk < 4; ++kk) {
            const int kc = kk * 16;
            uint32_t b[8][2];
#pragma unroll
            for (int np = 0; np < 4; ++np) {
                uint32_t addr = sBp + ((bBaseRow + np * 16) * TSTRIDE + kc + b_col) * 2;
                uint32_t r0, r1, r2, r3;
                ldsm_x4(r0, r1, r2, r3, addr);
                b[np*2][0] = r0; b[np*2][1] = r1;
                b[np*2+1][0] = r2; b[np*2+1][1] = r3;
            }
            uint32_t a[2][4];
#pragma unroll
            for (int mt = 0; mt < 2; ++mt) {
                uint32_t addr = sAp + ((aBaseRow + mt * 16) * TSTRIDE + kc + a_col) * 2;
                ldsm_x4(a[mt][0], a[mt][1], a[mt][2], a[mt][3], addr);
            }
#pragma unroll
            for (int mt = 0; mt < 2; ++mt)
#pragma unroll
                for (int nt = 0; nt < 8; ++nt)
                    mma_f16(acc[mt][nt], a[mt][0], a[mt][1], a[mt][2], a[mt][3],
                            b[nt][0], b[nt][1]);
        }
    }

    // -------- epilogue: split Q/K/V fp16 --------
    const int tr = lane >> 2;
    const int tc = (lane & 3) * 2;
#pragma unroll
    for (int mt = 0; mt < 2; ++mt) {
#pragma unroll
        for (int nt = 0; nt < 8; ++nt) {
            const int col = bx * 128 + wn * 64 + nt * 8 + tc;
            const float b0 = __ldg(bias + col);
            const float b1 = __ldg(bias + col + 1);
#pragma unroll
            for (int h2 = 0; h2 < 2; ++h2) {
                const int m = by * 128 + wm * 32 + mt * 16 + h2 * 8 + tr;
                float ox = acc[mt][nt][h2*2+0] + b0;
                float oy = acc[mt][nt][h2*2+1] + b1;
                const int seg = col >> 10;
                const int c = col & 1023;
                const int h = c >> 6;
                const int d = c & 63;
                const int bb = m >> 10, t = m & 1023;
                size_t idx = (((size_t)(bb * H_ + h)) * T_ + t) * D_ + d;
                if (seg == 0) { ox *= QSCALE; oy *= QSCALE; }  // fold 1/sqrt(D)*log2e
                uint32_t rw = pack_h2(__float2half(ox), __float2half(oy));
                __half* dst = (seg == 0) ? g_Qf : (seg == 1) ? g_Kf : g_Vf;
                *(uint32_t*)(dst + idx) = rw;
            }
        }
    }
}

// ---------------------------------------------------------------------------
// Output projection GEMM: 64x128 CTA tile, 8 warps (2M x 4N, warp 32x32),
// 2-stage cp.async, 3 CTAs/SM. fp32 out (+bias).
// ---------------------------------------------------------------------------
#define PAT_B  (64*TSTRIDE*2)            // 9216
#define PBT_B  (128*TSTRIDE*2)           // 18432
#define PSTG_B (PAT_B + PBT_B)           // 27648
#define PSMEM_TOTAL (2*PSTG_B)           // 55296

__global__ __launch_bounds__(256, 3)
void proj_kernel(const float* __restrict__ bias, float* __restrict__ Cout)
{
    extern __shared__ char smc[];
    const uint32_t sb = smem_u32(smc);
    const int tid = threadIdx.x;
    const int wid = tid >> 5, lane = tid & 31;
    const int bx = blockIdx.x, by = blockIdx.y;
    const int wm = wid & 1;
    const int wn = wid >> 1;

    const __half* Abf = g_A + (size_t)(by * 64) * KB_;
    const __half* Bbf = g_Bout + (size_t)(bx * 128) * KB_;

    const int lrow = tid >> 3;
    const int lch  = tid & 7;
    const uint32_t sOff = (uint32_t)(lrow * TSTRIDE * 2 + lch * 16);

    float acc[2][4][4];
#pragma unroll
    for (int i = 0; i < 2; i++)
#pragma unroll
        for (int j = 0; j < 4; j++)
#pragma unroll
            for (int v = 0; v < 4; v++) acc[i][j][v] = 0.f;

    const int a_row = (lane & 7) + ((lane >> 3) & 1) * 8;
    const int a_col = (lane >> 4) * 8;
    const int b_row = (lane & 7) + (lane >> 4) * 8;
    const int b_col = ((lane >> 3) & 1) * 8;
    const uint32_t aBaseRow = (uint32_t)(wm * 32 + a_row);
    const uint32_t bBaseRow = (uint32_t)(wn * 32 + b_row);

    auto load_stage = [&](int st, int ch) {
        const uint32_t sA = sb + st * PSTG_B + sOff;
        const uint32_t sB = sb + st * PSTG_B + PAT_B + sOff;
        const __half* Ag = Abf + (size_t)lrow * KB_ + ch * 64 + lch * 8;
        const __half* Bg = Bbf + (size_t)lrow * KB_ + ch * 64 + lch * 8;
#pragma unroll
        for (int i = 0; i < 2; i++)
            cp_async16(sA + i * 32 * TSTRIDE * 2, Ag + (size_t)(i * 32) * KB_);
#pragma unroll
        for (int i = 0; i < 4; i++)
            cp_async16(sB + i * 32 * TSTRIDE * 2, Bg + (size_t)(i * 32) * KB_);
    };

    load_stage(0, 0);
    CP_COMMIT();

    for (int ch = 0; ch < NCHB; ++ch) {
        CP_WAIT(0);
        __syncthreads();
        if (ch + 1 < NCHB) { load_stage((ch + 1) & 1, ch + 1); CP_COMMIT(); }

        const uint32_t sAp = sb + (ch & 1) * PSTG_B;
        const uint32_t sBp = sAp + PAT_B;
#pragma unroll
        for (int kk = 0; kk < 4; ++kk) {
            const int kc = kk * 16;
            uint32_t b[4][2];
#pragma unroll
            for (int np = 0; np < 2; ++np) {
                uint32_t addr = sBp + ((bBaseRow + np * 16) * TSTRIDE + kc + b_col) * 2;
                uint32_t r0, r1, r2, r3;
                ldsm_x4(r0, r1, r2, r3, addr);
                b[np*2][0] = r0; b[np*2][1] = r1;
                b[np*2+1][0] = r2; b[np*2+1][1] = r3;
            }
            uint32_t a[2][4];
#pragma unroll
            for (int mt = 0; mt < 2; ++mt) {
                uint32_t addr = sAp + ((aBaseRow + mt * 16) * TSTRIDE + kc + a_col) * 2;
                ldsm_x4(a[mt][0], a[mt][1], a[mt][2], a[mt][3], addr);
            }
#pragma unroll
            for (int mt = 0; mt < 2; ++mt)
#pragma unroll
                for (int nt = 0; nt < 4; ++nt)
                    mma_f16(acc[mt][nt], a[mt][0], a[mt][1], a[mt][2], a[mt][3],
                            b[nt][0], b[nt][1]);
        }
    }

    const int tr = lane >> 2;
    const int tc = (lane & 3) * 2;
#pragma unroll
    for (int mt = 0; mt < 2; ++mt) {
#pragma unroll
        for (int nt = 0; nt < 4; ++nt) {
            const int col = bx * 128 + wn * 32 + nt * 8 + tc;
            const float b0 = __ldg(bias + col);
            const float b1 = __ldg(bias + col + 1);
#pragma unroll
            for (int h2 = 0; h2 < 2; ++h2) {
                const int m = by * 64 + wm * 32 + mt * 16 + h2 * 8 + tr;
                *(float2*)(Cout + (size_t)m * Cc_ + col) =
                    make_float2(acc[mt][nt][h2*2+0] + b0, acc[mt][nt][h2*2+1] + b1);
            }
        }
    }
}

// ---------------------------------------------------------------------------
// fp16 HMMA flash attention (R14 best): 128 q-rows x (b,h), 8 warps x 16 rows.
// Stage = K/V for TWO kt tiles; single barrier per step. Softmax in log2
// domain (Q pre-scaled by log2e) -> bare exp2f. fp32-acc MMA throughout.
// ---------------------------------------------------------------------------
#define AST 72
#define QH_OFF 0
#define STG0   (128*AST*2)               // 18432
#define KTILE_B (64*AST*2)               // 9216
#define STG_B  (4*KTILE_B)               // 36864 (K0,V0,K1,V1)
#define ASMEM_TOTAL (STG0 + 2*STG_B)     // 92160

__global__ __launch_bounds__(256)
void attn_kernel()
{
    extern __shared__ char smc[];
    const uint32_t sb = smem_u32(smc);
    const int tid = threadIdx.x, wid = tid >> 5, lane = tid & 31;
    const int qt = gridDim.x - 1 - blockIdx.x;   // heavy tiles first
    const int bh = blockIdx.y;
    const int q0 = qt * 128;
    const size_t base = (size_t)bh * T_ * D_;

    {
        const __half* Qf = g_Qf + base + (size_t)q0 * D_;
#pragma unroll
        for (int i = 0; i < 4; i++) {
            int idx = tid + i * 256;
            int r = idx >> 3, c = idx & 7;
            cp_async16(sb + QH_OFF + (uint32_t)(r * AST + c * 8) * 2, Qf + (size_t)r * 64 + c * 8);
        }
        CP_COMMIT();
    }

    const int KT = 2 * qt + 2;   // always even

    auto load_stage = [&](int st, int kt0) {
        const uint32_t s0 = sb + STG0 + st * STG_B;
#pragma unroll
        for (int sub = 0; sub < 2; sub++) {
            const __half* srcs[2] = {
                g_Kf + base + (size_t)(kt0 + sub) * 64 * D_,
                g_Vf + base + (size_t)(kt0 + sub) * 64 * D_ };
#pragma unroll
            for (int tg = 0; tg < 2; tg++) {
#pragma unroll
                for (int it = 0; it < 2; it++) {
                    int r = (tid >> 3) + it * 32, c = tid & 7;
                    cp_async16(s0 + (sub * 2 + tg) * KTILE_B + (uint32_t)(r * AST + c * 8) * 2,
                               srcs[tg] + (size_t)r * 64 + c * 8);
                }
            }
        }
    };

    load_stage(0, 0); CP_COMMIT();

    const int a_row = (lane & 7) + ((lane >> 3) & 1) * 8;
    const int a_col = (lane >> 4) * 8;
    const int b_row = (lane & 7) + (lane >> 4) * 8;
    const int b_col = ((lane >> 3) & 1) * 8;
    const int v_row = lane & 15;
    const int v_col = (lane >> 4) * 8;
    const int wm = wid;

    uint32_t qh[4][4];
    float m_[2] = {-1e30f, -1e30f}, l_[2] = {0.f, 0.f};
    float oacc[8][4];
#pragma unroll
    for (int i = 0; i < 8; i++)
#pragma unroll
        for (int v = 0; v < 4; v++) oacc[i][v] = 0.f;

    const int rbase = q0 + wm * 16;

    for (int kt0 = 0; kt0 < KT; kt0 += 2) {
        CP_WAIT(0);              // current stage (and Q on first iter) resident
        __syncthreads();         // all warps done reading the other stage

        if (kt0 + 2 < KT) {      // issue next stage AFTER the barrier
            load_stage(((kt0 >> 1) + 1) & 1, kt0 + 2);
            CP_COMMIT();
        }

        if (kt0 == 0) {
#pragma unroll
            for (int ks = 0; ks < 4; ks++) {
                uint32_t aq = sb + QH_OFF + (uint32_t)((wm * 16 + a_row) * AST + ks * 16 + a_col) * 2;
                ldsm_x4(qh[ks][0], qh[ks][1], qh[ks][2], qh[ks][3], aq);
            }
        }

#pragma unroll
        for (int sub = 0; sub < 2; sub++) {
            const int kt = kt0 + sub;
            const bool active = (kt * 64) <= (rbase + 15);
            if (!active) continue;

            const uint32_t sKf = sb + STG0 + ((kt0 >> 1) & 1) * STG_B + sub * 2 * KTILE_B;
            const uint32_t sVf = sKf + KTILE_B;

            // ---- S = Q*K (log2 units) ----
            float sacc[8][4];
#pragma unroll
            for (int i = 0; i < 8; i++)
#pragma unroll
                for (int v = 0; v < 4; v++) sacc[i][v] = 0.f;

#pragma unroll
            for (int ks = 0; ks < 4; ks++) {
                uint32_t kf[4][4];
#pragma unroll
                for (int np = 0; np < 4; np++) {
                    uint32_t addr = sKf + (uint32_t)((np * 16 + b_row) * AST + ks * 16 + b_col) * 2;
                    ldsm_x4(kf[np][0], kf[np][1], kf[np][2], kf[np][3], addr);
                }
#pragma unroll
                for (int np = 0; np < 4; np++) {
                    mma_f16(sacc[2*np],   qh[ks][0], qh[ks][1], qh[ks][2], qh[ks][3], kf[np][0], kf[np][1]);
                    mma_f16(sacc[2*np+1], qh[ks][0], qh[ks][1], qh[ks][2], qh[ks][3], kf[np][2], kf[np][3]);
                }
            }

            if (kt * 64 + 63 > rbase) {
                const int r0r = rbase + (lane >> 2);
#pragma unroll
                for (int nt = 0; nt < 8; nt++) {
#pragma unroll
                    for (int v = 0; v < 4; v++) {
                        int col = kt * 64 + nt * 8 + 2 * (lane & 3) + (v & 1);
                        int row = r0r + (v >> 1) * 8;
                        if (col > row) sacc[nt][v] = -1e30f;
                    }
                }
            }

            // ---- online softmax, log2 domain ----
            float alpha[2];
#pragma unroll
            for (int h2 = 0; h2 < 2; h2++) {
                float mx = -1e30f;
#pragma unroll
                for (int nt = 0; nt < 8; nt++)
                    mx = fmaxf(mx, fmaxf(sacc[nt][2*h2], sacc[nt][2*h2+1]));
                mx = fmaxf(mx, __shfl_xor_sync(0xffffffffu, mx, 1));
                mx = fmaxf(mx, __shfl_xor_sync(0xffffffffu, mx, 2));
                float mnew = fmaxf(m_[h2], mx);
                alpha[h2] = exp2f(m_[h2] - mnew);
                float rs = 0.f;
#pragma unroll
                for (int nt = 0; nt < 8; nt++) {
                    sacc[nt][2*h2]   = exp2f(sacc[nt][2*h2]   - mnew);
                    sacc[nt][2*h2+1] = exp2f(sacc[nt][2*h2+1] - mnew);
                    rs += sacc[nt][2*h2] + sacc[nt][2*h2+1];
                }
                rs += __shfl_xor_sync(0xffffffffu, rs, 1);
                rs += __shfl_xor_sync(0xffffffffu, rs, 2);
                l_[h2] = l_[h2] * alpha[h2] + rs;
                m_[h2] = mnew;
            }
#pragma unroll
            for (int dt = 0; dt < 8; dt++) {
                oacc[dt][0] *= alpha[0]; oacc[dt][1] *= alpha[0];
                oacc[dt][2] *= alpha[1]; oacc[dt][3] *= alpha[1];
            }

            // ---- O += P*V ----
#pragma unroll
            for (int ks = 0; ks < 4; ks++) {
                uint32_t ph[4];
                ph[0] = pack_h2(__float2half(sacc[2*ks][0]),   __float2half(sacc[2*ks][1]));
                ph[1] = pack_h2(__float2half(sacc[2*ks][2]),   __float2half(sacc[2*ks][3]));
                ph[2] = pack_h2(__float2half(sacc[2*ks+1][0]), __float2half(sacc[2*ks+1][1]));
                ph[3] = pack_h2(__float2half(sacc[2*ks+1][2]), __float2half(sacc[2*ks+1][3]));

                uint32_t vf[4][4];
#pragma unroll
                for (int nt2 = 0; nt2 < 4; nt2++) {
                    uint32_t addr = sVf + (uint32_t)((ks * 16 + v_row) * AST + nt2 * 16 + v_col) * 2;
                    ldsm_x4_t(vf[nt2][0], vf[nt2][1], vf[nt2][2], vf[nt2][3], addr);
                }
#pragma unroll
                for (int nt2 = 0; nt2 < 4; nt2++) {
                    mma_f16(oacc[2*nt2],   ph[0], ph[1], ph[2], ph[3], vf[nt2][0], vf[nt2][1]);
                    mma_f16(oacc[2*nt2+1], ph[0], ph[1], ph[2], ph[3], vf[nt2][2], vf[nt2][3]);
                }
            }
        }
    }

    // ---- epilogue: O/l rounded fp16 -> g_A ----
    const int bb = bh >> 4, hh = bh & 15;
    const float inv0 = 1.f / l_[0], inv1 = 1.f / l_[1];
#pragma unroll
    for (int dt = 0; dt < 8; dt++) {
#pragma unroll
        for (int h2 = 0; h2 < 2; h2++) {
            const int rloc = wm * 16 + (lane >> 2) + h2 * 8;
            const int d = dt * 8 + 2 * (lane & 3);
            const float inv = h2 ? inv1 : inv0;
            float ox = oacc[dt][2*h2]   * inv;
            float oy = oacc[dt][2*h2+1] * inv;
            uint32_t rw = pack_h2(__float2half(ox), __float2half(oy));
            const size_t mrow = (size_t)(bb * T_ + q0 + rloc);
            *(uint32_t*)(g_A + mrow * Cc_ + hh * 64 + d) = rw;
        }
    }
}

// ---------------------------------------------------------------------------
extern "C" void kernel_launch(void* const* d_in, const int* in_sizes, int n_in,
                              void* d_out, int out_size)
{
    const float* x    = (const float*)d_in[0];
    const float* Wqkv = (const float*)d_in[1];
    const float* bqkv = (const float*)d_in[2];
    const float* Wout = (const float*)d_in[3];
    const float* bout = (const float*)d_in[4];
    float* out = (float*)d_out;

    cudaFuncSetAttribute(qkv_kernel,
                         cudaFuncAttributeMaxDynamicSharedMemorySize, GSMEM_TOTAL);
    cudaFuncSetAttribute(proj_kernel,
                         cudaFuncAttributeMaxDynamicSharedMemorySize, PSMEM_TOTAL);
    cudaFuncSetAttribute(attn_kernel,
                         cudaFuncAttributeMaxDynamicSharedMemorySize, ASMEM_TOTAL);

    // 0) fused conversions (x widened to 16B stores; Wqkv, Wout -> fp16)
    conv_all<<<4096 + 3072 + 1024, 256>>>(x, Wqkv, Wout);

    // 1) QKV projection -> Q(x0.125*log2e)/K/V fp16 [B,H,T,D]
    qkv_kernel<<<dim3(N3_/128, M_/128), 256, GSMEM_TOTAL>>>(bqkv);

    // 2) fp16 HMMA causal flash attention (fp32-acc, single barrier, exp2) -> g_A
    attn_kernel<<<dim3(T_/128, BH_), 256, ASMEM_TOTAL>>>();

    // 3) output projection (64x128 tiles, 3 CTAs/SM) -> d_out
    proj_kernel<<<dim3(Cc_/128, M_/64), 256, PSMEM_TOTAL>>>(bout, out);
}

// round 17
// speedup vs baseline: 1.5240x; 1.5240x over previous
#include <cuda_runtime.h>
#include <cuda_fp16.h>
#include <cstdint>

// Problem constants
#define B_   8
#define T_   1024
#define Cc_  1024
#define H_   16
#define D_   64
#define BH_  (B_*H_)     // 128
#define M_   (B_*T_)     // 8192
#define N3_  3072
#define KB_  Cc_         // 1024

// Scratch (static device globals: allocation-free)
__device__ __half g_Qf[(size_t)BH_*T_*D_];
__device__ __half g_Kf[(size_t)BH_*T_*D_];
__device__ __half g_Vf[(size_t)BH_*T_*D_];
__device__ __half g_A[(size_t)M_*Cc_];       // acts fp16: x for QKV, then O for proj
__device__ __half g_Bqkv[(size_t)N3_*KB_];
__device__ __half g_Bout[(size_t)Cc_*KB_];

// ---------------------------------------------------------------------------
__device__ __forceinline__ uint32_t smem_u32(const void* p) {
    uint32_t a;
    asm("{ .reg .u64 t; cvta.to.shared.u64 t, %1; cvt.u32.u64 %0, t; }"
        : "=r"(a) : "l"(p));
    return a;
}
__device__ __forceinline__ void ldsm_x4(uint32_t& r0, uint32_t& r1,
                                        uint32_t& r2, uint32_t& r3, uint32_t addr) {
    asm volatile("ldmatrix.sync.aligned.m8n8.x4.shared.b16 {%0,%1,%2,%3}, [%4];"
                 : "=r"(r0), "=r"(r1), "=r"(r2), "=r"(r3) : "r"(addr));
}
__device__ __forceinline__ void ldsm_x4_t(uint32_t& r0, uint32_t& r1,
                                          uint32_t& r2, uint32_t& r3, uint32_t addr) {
    asm volatile("ldmatrix.sync.aligned.m8n8.x4.trans.shared.b16 {%0,%1,%2,%3}, [%4];"
                 : "=r"(r0), "=r"(r1), "=r"(r2), "=r"(r3) : "r"(addr));
}
__device__ __forceinline__ void mma_f16(float* d, uint32_t a0, uint32_t a1,
                                        uint32_t a2, uint32_t a3,
                                        uint32_t b0, uint32_t b1) {
    asm volatile(
        "mma.sync.aligned.m16n8k16.row.col.f32.f16.f16.f32 "
        "{%0,%1,%2,%3}, {%4,%5,%6,%7}, {%8,%9}, {%0,%1,%2,%3};"
        : "+f"(d[0]), "+f"(d[1]), "+f"(d[2]), "+f"(d[3])
        : "r"(a0), "r"(a1), "r"(a2), "r"(a3), "r"(b0), "r"(b1));
}
__device__ __forceinline__ void cp_async16(uint32_t saddr, const void* gaddr) {
    asm volatile("cp.async.cg.shared.global [%0], [%1], 16;"
                 :: "r"(saddr), "l"(gaddr));
}
#define CP_COMMIT() asm volatile("cp.async.commit_group;" ::: "memory")
#define CP_WAIT(n)  asm volatile("cp.async.wait_group %0;" :: "n"(n) : "memory")

__device__ __forceinline__ uint32_t pack_h2(__half a, __half b) {
    return (uint32_t)__half_as_ushort(a) | ((uint32_t)__half_as_ushort(b) << 16);
}

// ---------------------------------------------------------------------------
// Fused conversion kernel: blocks [0,8192) x->g_A; [8192,11264) Wqkv->g_Bqkv;
// [11264,12288) Wout->g_Bout.
// ---------------------------------------------------------------------------
__global__ __launch_bounds__(256)
void conv_all(const float* __restrict__ x,
              const float* __restrict__ Wq,
              const float* __restrict__ Wo)
{
    __shared__ float tile[32][33];
    const int t = threadIdx.x;
    const int b = blockIdx.x;

    if (b < 8192) {            // activations
        int idx = b * 256 + t;
        int m  = idx >> 8;
        int k4 = (idx & 255) << 2;
        float4 v = *(const float4*)(x + (size_t)m * Cc_ + k4);
        uint2 w = make_uint2(pack_h2(__float2half(v.x), __float2half(v.y)),
                             pack_h2(__float2half(v.z), __float2half(v.w)));
        *(uint2*)(g_A + (size_t)m * Cc_ + k4) = w;
        return;
    }

    const float* W;
    __half* Bt;
    int N, bi;
    if (b < 8192 + 3072) { bi = b - 8192;        W = Wq; Bt = g_Bqkv; N = N3_; }
    else                 { bi = b - 8192 - 3072; W = Wo; Bt = g_Bout; N = Cc_; }
    const int k0 = (bi & 31) * 32;
    const int n0 = (bi >> 5) * 32;
#pragma unroll
    for (int i = 0; i < 4; i++) {
        int r = (t >> 5) + i * 8;
        int c = t & 31;
        tile[r][c] = W[(size_t)(k0 + r) * N + n0 + c];
    }
    __syncthreads();
#pragma unroll
    for (int i = 0; i < 4; i++) {
        int nr = (t >> 5) + i * 8;
        int kc = t & 31;
        Bt[(size_t)(n0 + nr) * KB_ + k0 + kc] = __float2half(tile[kc][nr]);
    }
}

// ---------------------------------------------------------------------------
// QKV GEMM: 128x128 CTA tile, BK=64, 8 warps (4M x 2N, warp 32x64), 3-stage
// cp.async, one barrier per chunk. Epilogue -> Q(x0.125*log2e)/K/V fp16.
// ---------------------------------------------------------------------------
#define TSTRIDE 72
#define TILE_B  (128*TSTRIDE*2)          // 18432
#define STAGE_B (2*TILE_B)               // 36864
#define NSTAGE  3
#define GSMEM_TOTAL (NSTAGE*STAGE_B)     // 110592
#define NCHB    (KB_/64)                 // 16
#define QSCALE  (0.125f * 1.4426950408889634f)   // 1/sqrt(D) * log2(e)

__global__ __launch_bounds__(256)
void qkv_kernel(const float* __restrict__ bias)
{
    extern __shared__ char smc[];
    const uint32_t sb = smem_u32(smc);
    const int tid = threadIdx.x;
    const int wid = tid >> 5, lane = tid & 31;
    const int bx = blockIdx.x, by = blockIdx.y;
    const int wm = wid & 3;
    const int wn = wid >> 2;

    const __half* Abf = g_A + (size_t)(by * 128) * KB_;
    const __half* Bbf = g_Bqkv + (size_t)(bx * 128) * KB_;

    const int lrow = tid >> 3;
    const int lch  = tid & 7;
    const uint32_t sOff = (uint32_t)(lrow * TSTRIDE * 2 + lch * 16);

    float acc[2][8][4];
#pragma unroll
    for (int i = 0; i < 2; i++)
#pragma unroll
        for (int j = 0; j < 8; j++)
#pragma unroll
            for (int v = 0; v < 4; v++) acc[i][j][v] = 0.f;

    const int a_row = (lane & 7) + ((lane >> 3) & 1) * 8;
    const int a_col = (lane >> 4) * 8;
    const int b_row = (lane & 7) + (lane >> 4) * 8;
    const int b_col = ((lane >> 3) & 1) * 8;
    const uint32_t aBaseRow = (uint32_t)(wm * 32 + a_row);
    const uint32_t bBaseRow = (uint32_t)(wn * 64 + b_row);

    auto load_stage = [&](int st, int ch) {
        const uint32_t sA = sb + st * STAGE_B + sOff;
        const uint32_t sB = sA + TILE_B;
        const __half* Ag = Abf + (size_t)lrow * KB_ + ch * 64 + lch * 8;
        const __half* Bg = Bbf + (size_t)lrow * KB_ + ch * 64 + lch * 8;
#pragma unroll
        for (int i = 0; i < 4; i++) {
            cp_async16(sA + i * 32 * TSTRIDE * 2, Ag + (size_t)(i * 32) * KB_);
            cp_async16(sB + i * 32 * TSTRIDE * 2, Bg + (size_t)(i * 32) * KB_);
        }
    };

#pragma unroll
    for (int s = 0; s < NSTAGE - 1; ++s) {
        load_stage(s, s);
        CP_COMMIT();
    }

    for (int ch = 0; ch < NCHB; ++ch) {
        CP_WAIT(NSTAGE - 2);
        __syncthreads();

        const int lc = ch + NSTAGE - 1;
        if (lc < NCHB) load_stage(lc % NSTAGE, lc);
        CP_COMMIT();

        const uint32_t sAp = sb + (ch % NSTAGE) * STAGE_B;
        const uint32_t sBp = sAp + TILE_B;
#pragma unroll
        for (int kk = 0; kk < 4; ++kk) {
            const int kc = kk * 16;
            uint32_t b[8][2];
#pragma unroll
            for (int np = 0; np < 4; ++np) {
                uint32_t addr = sBp + ((bBaseRow + np * 16) * TSTRIDE + kc + b_col) * 2;
                uint32_t r0, r1, r2, r3;
                ldsm_x4(r0, r1, r2, r3, addr);
                b[np*2][0] = r0; b[np*2][1] = r1;
                b[np*2+1][0] = r2; b[np*2+1][1] = r3;
            }
            uint32_t a[2][4];
#pragma unroll
            for (int mt = 0; mt < 2; ++mt) {
                uint32_t addr = sAp + ((aBaseRow + mt * 16) * TSTRIDE + kc + a_col) * 2;
                ldsm_x4(a[mt][0], a[mt][1], a[mt][2], a[mt][3], addr);
            }
#pragma unroll
            for (int mt = 0; mt < 2; ++mt)
#pragma unroll
                for (int nt = 0; nt < 8; ++nt)
                    mma_f16(acc[mt][nt], a[mt][0], a[mt][1], a[mt][2], a[mt][3],
                            b[nt][0], b[nt][1]);
        }
    }

    // -------- epilogue: split Q/K/V fp16 --------
    const int tr = lane >> 2;
    const int tc = (lane & 3) * 2;
#pragma unroll
    for (int mt = 0; mt < 2; ++mt) {
#pragma unroll
        for (int nt = 0; nt < 8; ++nt) {
            const int col = bx * 128 + wn * 64 + nt * 8 + tc;
            const float b0 = __ldg(bias + col);
            const float b1 = __ldg(bias + col + 1);
#pragma unroll
            for (int h2 = 0; h2 < 2; ++h2) {
                const int m = by * 128 + wm * 32 + mt * 16 + h2 * 8 + tr;
                float ox = acc[mt][nt][h2*2+0] + b0;
                float oy = acc[mt][nt][h2*2+1] + b1;
                const int seg = col >> 10;
                const int c = col & 1023;
                const int h = c >> 6;
                const int d = c & 63;
                const int bb = m >> 10, t = m & 1023;
                size_t idx = (((size_t)(bb * H_ + h)) * T_ + t) * D_ + d;
                if (seg == 0) { ox *= QSCALE; oy *= QSCALE; }  // fold 1/sqrt(D)*log2e
                uint32_t rw = pack_h2(__float2half(ox), __float2half(oy));
                __half* dst = (seg == 0) ? g_Qf : (seg == 1) ? g_Kf : g_Vf;
                *(uint32_t*)(dst + idx) = rw;
            }
        }
    }
}

// ---------------------------------------------------------------------------
// Output projection GEMM: 64x128 CTA tile, 8 warps (2M x 4N, warp 32x32),
// 2-stage cp.async, 3 CTAs/SM. fp32 out (+bias).
// ---------------------------------------------------------------------------
#define PAT_B  (64*TSTRIDE*2)            // 9216
#define PBT_B  (128*TSTRIDE*2)           // 18432
#define PSTG_B (PAT_B + PBT_B)           // 27648
#define PSMEM_TOTAL (2*PSTG_B)           // 55296

__global__ __launch_bounds__(256, 3)
void proj_kernel(const float* __restrict__ bias, float* __restrict__ Cout)
{
    extern __shared__ char smc[];
    const uint32_t sb = smem_u32(smc);
    const int tid = threadIdx.x;
    const int wid = tid >> 5, lane = tid & 31;
    const int bx = blockIdx.x, by = blockIdx.y;
    const int wm = wid & 1;
    const int wn = wid >> 1;

    const __half* Abf = g_A + (size_t)(by * 64) * KB_;
    const __half* Bbf = g_Bout + (size_t)(bx * 128) * KB_;

    const int lrow = tid >> 3;
    const int lch  = tid & 7;
    const uint32_t sOff = (uint32_t)(lrow * TSTRIDE * 2 + lch * 16);

    float acc[2][4][4];
#pragma unroll
    for (int i = 0; i < 2; i++)
#pragma unroll
        for (int j = 0; j < 4; j++)
#pragma unroll
            for (int v = 0; v < 4; v++) acc[i][j][v] = 0.f;

    const int a_row = (lane & 7) + ((lane >> 3) & 1) * 8;
    const int a_col = (lane >> 4) * 8;
    const int b_row = (lane & 7) + (lane >> 4) * 8;
    const int b_col = ((lane >> 3) & 1) * 8;
    const uint32_t aBaseRow = (uint32_t)(wm * 32 + a_row);
    const uint32_t bBaseRow = (uint32_t)(wn * 32 + b_row);

    auto load_stage = [&](int st, int ch) {
        const uint32_t sA = sb + st * PSTG_B + sOff;
        const uint32_t sB = sb + st * PSTG_B + PAT_B + sOff;
        const __half* Ag = Abf + (size_t)lrow * KB_ + ch * 64 + lch * 8;
        const __half* Bg = Bbf + (size_t)lrow * KB_ + ch * 64 + lch * 8;
#pragma unroll
        for (int i = 0; i < 2; i++)
            cp_async16(sA + i * 32 * TSTRIDE * 2, Ag + (size_t)(i * 32) * KB_);
#pragma unroll
        for (int i = 0; i < 4; i++)
            cp_async16(sB + i * 32 * TSTRIDE * 2, Bg + (size_t)(i * 32) * KB_);
    };

    load_stage(0, 0);
    CP_COMMIT();

    for (int ch = 0; ch < NCHB; ++ch) {
        CP_WAIT(0);
        __syncthreads();
        if (ch + 1 < NCHB) { load_stage((ch + 1) & 1, ch + 1); CP_COMMIT(); }

        const uint32_t sAp = sb + (ch & 1) * PSTG_B;
        const uint32_t sBp = sAp + PAT_B;
#pragma unroll
        for (int kk = 0; kk < 4; ++kk) {
            const int kc = kk * 16;
            uint32_t b[4][2];
#pragma unroll
            for (int np = 0; np < 2; ++np) {
                uint32_t addr = sBp + ((bBaseRow + np * 16) * TSTRIDE + kc + b_col) * 2;
                uint32_t r0, r1, r2, r3;
                ldsm_x4(r0, r1, r2, r3, addr);
                b[np*2][0] = r0; b[np*2][1] = r1;
                b[np*2+1][0] = r2; b[np*2+1][1] = r3;
            }
            uint32_t a[2][4];
#pragma unroll
            for (int mt = 0; mt < 2; ++mt) {
                uint32_t addr = sAp + ((aBaseRow + mt * 16) * TSTRIDE + kc + a_col) * 2;
                ldsm_x4(a[mt][0], a[mt][1], a[mt][2], a[mt][3], addr);
            }
#pragma unroll
            for (int mt = 0; mt < 2; ++mt)
#pragma unroll
                for (int nt = 0; nt < 4; ++nt)
                    mma_f16(acc[mt][nt], a[mt][0], a[mt][1], a[mt][2], a[mt][3],
                            b[nt][0], b[nt][1]);
        }
    }

    const int tr = lane >> 2;
    const int tc = (lane & 3) * 2;
#pragma unroll
    for (int mt = 0; mt < 2; ++mt) {
#pragma unroll
        for (int nt = 0; nt < 4; ++nt) {
            const int col = bx * 128 + wn * 32 + nt * 8 + tc;
            const float b0 = __ldg(bias + col);
            const float b1 = __ldg(bias + col + 1);
#pragma unroll
            for (int h2 = 0; h2 < 2; ++h2) {
                const int m = by * 64 + wm * 32 + mt * 16 + h2 * 8 + tr;
                *(float2*)(Cout + (size_t)m * Cc_ + col) =
                    make_float2(acc[mt][nt][h2*2+0] + b0, acc[mt][nt][h2*2+1] + b1);
            }
        }
    }
}

// ---------------------------------------------------------------------------
// fp16 HMMA flash attention: 128 q-rows x (b,h), 8 warps x 16 rows.
// Stage = K/V for TWO kt tiles; single barrier per step. Softmax in log2
// domain (Q pre-scaled by log2e) -> bare exp2f. fp32-acc MMA throughout.
// ---------------------------------------------------------------------------
#define AST 72
#define QH_OFF 0
#define STG0   (128*AST*2)               // 18432
#define KTILE_B (64*AST*2)               // 9216
#define STG_B  (4*KTILE_B)               // 36864 (K0,V0,K1,V1)
#define ASMEM_TOTAL (STG0 + 2*STG_B)     // 92160

__global__ __launch_bounds__(256)
void attn_kernel()
{
    extern __shared__ char smc[];
    const uint32_t sb = smem_u32(smc);
    const int tid = threadIdx.x, wid = tid >> 5, lane = tid & 31;
    const int qt = gridDim.x - 1 - blockIdx.x;   // heavy tiles first
    const int bh = blockIdx.y;
    const int q0 = qt * 128;
    const size_t base = (size_t)bh * T_ * D_;

    {
        const __half* Qf = g_Qf + base + (size_t)q0 * D_;
#pragma unroll
        for (int i = 0; i < 4; i++) {
            int idx = tid + i * 256;
            int r = idx >> 3, c = idx & 7;
            cp_async16(sb + QH_OFF + (uint32_t)(r * AST + c * 8) * 2, Qf + (size_t)r * 64 + c * 8);
        }
        CP_COMMIT();
    }

    const int KT = 2 * qt + 2;   // always even

    auto load_stage = [&](int st, int kt0) {
        const uint32_t s0 = sb + STG0 + st * STG_B;
#pragma unroll
        for (int sub = 0; sub < 2; sub++) {
            const __half* srcs[2] = {
                g_Kf + base + (size_t)(kt0 + sub) * 64 * D_,
                g_Vf + base + (size_t)(kt0 + sub) * 64 * D_ };
#pragma unroll
            for (int tg = 0; tg < 2; tg++) {
#pragma unroll
                for (int it = 0; it < 2; it++) {
                    int r = (tid >> 3) + it * 32, c = tid & 7;
                    cp_async16(s0 + (sub * 2 + tg) * KTILE_B + (uint32_t)(r * AST + c * 8) * 2,
                               srcs[tg] + (size_t)r * 64 + c * 8);
                }
            }
        }
    };

    load_stage(0, 0); CP_COMMIT();

    const int a_row = (lane & 7) + ((lane >> 3) & 1) * 8;
    const int a_col = (lane >> 4) * 8;
    const int b_row = (lane & 7) + (lane >> 4) * 8;
    const int b_col = ((lane >> 3) & 1) * 8;
    const int v_row = lane & 15;
    const int v_col = (lane >> 4) * 8;
    const int wm = wid;

    uint32_t qh[4][4];
    float m_[2] = {-1e30f, -1e30f}, l_[2] = {0.f, 0.f};
    float oacc[8][4];
#pragma unroll
    for (int i = 0; i < 8; i++)
#pragma unroll
        for (int v = 0; v < 4; v++) oacc[i][v] = 0.f;

    const int rbase = q0 + wm * 16;

    for (int kt0 = 0; kt0 < KT; kt0 += 2) {
        CP_WAIT(0);              // current stage (and Q on first iter) resident
        __syncthreads();         // all warps done reading the other stage

        if (kt0 + 2 < KT) {      // issue next stage AFTER the barrier
            load_stage(((kt0 >> 1) + 1) & 1, kt0 + 2);
            CP_COMMIT();
        }

        if (kt0 == 0) {
#pragma unroll
            for (int ks = 0; ks < 4; ks++) {
                uint32_t aq = sb + QH_OFF + (uint32_t)((wm * 16 + a_row) * AST + ks * 16 + a_col) * 2;
                ldsm_x4(qh[ks][0], qh[ks][1], qh[ks][2], qh[ks][3], aq);
            }
        }

#pragma unroll
        for (int sub = 0; sub < 2; sub++) {
            const int kt = kt0 + sub;
            const bool active = (kt * 64) <= (rbase + 15);
            if (!active) continue;

            const uint32_t sKf = sb + STG0 + ((kt0 >> 1) & 1) * STG_B + sub * 2 * KTILE_B;
            const uint32_t sVf = sKf + KTILE_B;

            // ---- S = Q*K (log2 units) ----
            float sacc[8][4];
#pragma unroll
            for (int i = 0; i < 8; i++)
#pragma unroll
                for (int v = 0; v < 4; v++) sacc[i][v] = 0.f;

#pragma unroll
            for (int ks = 0; ks < 4; ks++) {
                uint32_t kf[4][4];
#pragma unroll
                for (int np = 0; np < 4; np++) {
                    uint32_t addr = sKf + (uint32_t)((np * 16 + b_row) * AST + ks * 16 + b_col) * 2;
                    ldsm_x4(kf[np][0], kf[np][1], kf[np][2], kf[np][3], addr);
                }
#pragma unroll
                for (int np = 0; np < 4; np++) {
                    mma_f16(sacc[2*np],   qh[ks][0], qh[ks][1], qh[ks][2], qh[ks][3], kf[np][0], kf[np][1]);
                    mma_f16(sacc[2*np+1], qh[ks][0], qh[ks][1], qh[ks][2], qh[ks][3], kf[np][2], kf[np][3]);
                }
            }

            if (kt * 64 + 63 > rbase) {
                const int r0r = rbase + (lane >> 2);
#pragma unroll
                for (int nt = 0; nt < 8; nt++) {
#pragma unroll
                    for (int v = 0; v < 4; v++) {
                        int col = kt * 64 + nt * 8 + 2 * (lane & 3) + (v & 1);
                        int row = r0r + (v >> 1) * 8;
                        if (col > row) sacc[nt][v] = -1e30f;
                    }
                }
            }

            // ---- online softmax, log2 domain ----
            float alpha[2];
#pragma unroll
            for (int h2 = 0; h2 < 2; h2++) {
                float mx = -1e30f;
#pragma unroll
                for (int nt = 0; nt < 8; nt++)
                    mx = fmaxf(mx, fmaxf(sacc[nt][2*h2], sacc[nt][2*h2+1]));
                mx = fmaxf(mx, __shfl_xor_sync(0xffffffffu, mx, 1));
                mx = fmaxf(mx, __shfl_xor_sync(0xffffffffu, mx, 2));
                float mnew = fmaxf(m_[h2], mx);
                alpha[h2] = exp2f(m_[h2] - mnew);
                float rs = 0.f;
#pragma unroll
                for (int nt = 0; nt < 8; nt++) {
                    sacc[nt][2*h2]   = exp2f(sacc[nt][2*h2]   - mnew);
                    sacc[nt][2*h2+1] = exp2f(sacc[nt][2*h2+1] - mnew);
                    rs += sacc[nt][2*h2] + sacc[nt][2*h2+1];
                }
                rs += __shfl_xor_sync(0xffffffffu, rs, 1);
                rs += __shfl_xor_sync(0xffffffffu, rs, 2);
                l_[h2] = l_[h2] * alpha[h2] + rs;
                m_[h2] = mnew;
            }
#pragma unroll
            for (int dt = 0; dt < 8; dt++) {
                oacc[dt][0] *= alpha[0]; oacc[dt][1] *= alpha[0];
                oacc[dt][2] *= alpha[1]; oacc[dt][3] *= alpha[1];
            }

            // ---- O += P*V ----
#pragma unroll
            for (int ks = 0; ks < 4; ks++) {
                uint32_t ph[4];
                ph[0] = pack_h2(__float2half(sacc[2*ks][0]),   __float2half(sacc[2*ks][1]));
                ph[1] = pack_h2(__float2half(sacc[2*ks][2]),   __float2half(sacc[2*ks][3]));
                ph[2] = pack_h2(__float2half(sacc[2*ks+1][0]), __float2half(sacc[2*ks+1][1]));
                ph[3] = pack_h2(__float2half(sacc[2*ks+1][2]), __float2half(sacc[2*ks+1][3]));

                uint32_t vf[4][4];
#pragma unroll
                for (int nt2 = 0; nt2 < 4; nt2++) {
                    uint32_t addr = sVf + (uint32_t)((ks * 16 + v_row) * AST + nt2 * 16 + v_col) * 2;
                    ldsm_x4_t(vf[nt2][0], vf[nt2][1], vf[nt2][2], vf[nt2][3], addr);
                }
#pragma unroll
                for (int nt2 = 0; nt2 < 4; nt2++) {
                    mma_f16(oacc[2*nt2],   ph[0], ph[1], ph[2], ph[3], vf[nt2][0], vf[nt2][1]);
                    mma_f16(oacc[2*nt2+1], ph[0], ph[1], ph[2], ph[3], vf[nt2][2], vf[nt2][3]);
                }
            }
        }
    }

    // ---- epilogue: O/l rounded fp16 -> g_A ----
    const int bb = bh >> 4, hh = bh & 15;
    const float inv0 = 1.f / l_[0], inv1 = 1.f / l_[1];
#pragma unroll
    for (int dt = 0; dt < 8; dt++) {
#pragma unroll
        for (int h2 = 0; h2 < 2; h2++) {
            const int rloc = wm * 16 + (lane >> 2) + h2 * 8;
            const int d = dt * 8 + 2 * (lane & 3);
            const float inv = h2 ? inv1 : inv0;
            float ox = oacc[dt][2*h2]   * inv;
            float oy = oacc[dt][2*h2+1] * inv;
            uint32_t rw = pack_h2(__float2half(ox), __float2half(oy));
            const size_t mrow = (size_t)(bb * T_ + q0 + rloc);
            *(uint32_t*)(g_A + mrow * Cc_ + hh * 64 + d) = rw;
        }
    }
}

// ---------------------------------------------------------------------------
extern "C" void kernel_launch(void* const* d_in, const int* in_sizes, int n_in,
                              void* d_out, int out_size)
{
    const float* x    = (const float*)d_in[0];
    const float* Wqkv = (const float*)d_in[1];
    const float* bqkv = (const float*)d_in[2];
    const float* Wout = (const float*)d_in[3];
    const float* bout = (const float*)d_in[4];
    float* out = (float*)d_out;

    cudaFuncSetAttribute(qkv_kernel,
                         cudaFuncAttributeMaxDynamicSharedMemorySize, GSMEM_TOTAL);
    cudaFuncSetAttribute(proj_kernel,
                         cudaFuncAttributeMaxDynamicSharedMemorySize, PSMEM_TOTAL);
    cudaFuncSetAttribute(attn_kernel,
                         cudaFuncAttributeMaxDynamicSharedMemorySize, ASMEM_TOTAL);

    // 0) fused conversions (x, Wqkv, Wout -> fp16)
    conv_all<<<8192 + 3072 + 1024, 256>>>(x, Wqkv, Wout);

    // 1) QKV projection -> Q(x0.125*log2e)/K/V fp16 [B,H,T,D]
    qkv_kernel<<<dim3(N3_/128, M_/128), 256, GSMEM_TOTAL>>>(bqkv);

    // 2) fp16 HMMA causal flash attention (single barrier, exp2) -> g_A
    attn_kernel<<<dim3(T_/128, BH_), 256, ASMEM_TOTAL>>>();

    // 3) output projection (64x128 tiles, 3 CTAs/SM) -> d_out
    proj_kernel<<<dim3(Cc_/128, M_/64), 256, PSMEM_TOTAL>>>(bout, out);
}